// round 9
// baseline (speedup 1.0000x reference)
#include <cuda_runtime.h>
#include <cuda_bf16.h>
#include <cuda_fp16.h>
#include <cstdint>

#define N_NODES 100000
#define N_EDGES 1600000
#define F 128
#define SCAN_B 1024
#define NPART ((N_NODES + SCAN_B - 1) / SCAN_B)   // 98

// ---------------- device scratch (allocation-free rule) ----------------
__device__ __align__(16) __half g_h16a[(size_t)N_NODES * F];  // 25.6 MB (layer-1 input)
__device__ __align__(16) __half g_h16b[(size_t)N_NODES * F];  // 25.6 MB (layer-1 output)
__device__ int   g_deg_src[N_NODES];
__device__ int   g_deg_dst[N_NODES];
__device__ float g_rs_src[N_NODES];
__device__ float g_rs_dst[N_NODES];
__device__ int   g_rowptr[N_NODES + 1];
__device__ int   g_cursor[N_NODES];
__device__ int   g_col[N_EDGES];                  // 6.4 MB
__device__ int   g_part[NPART];
__device__ __align__(16) unsigned short g_Whi[2][128 * 128];
__device__ __align__(16) unsigned short g_Wlo[2][128 * 128];

// ---------------- mma.sync helpers ----------------
__device__ __forceinline__ uint32_t smem_u32(const void* p) {
    uint32_t a;
    asm("{ .reg .u64 t; cvta.to.shared.u64 t, %1; cvt.u32.u64 %0, t; }"
        : "=r"(a) : "l"(p));
    return a;
}
#define LDSM_X4(r, addr) \
    asm volatile("ldmatrix.sync.aligned.m8n8.x4.shared.b16 {%0,%1,%2,%3}, [%4];" \
                 : "=r"((r)[0]), "=r"((r)[1]), "=r"((r)[2]), "=r"((r)[3]) \
                 : "r"(addr))
#define LDSM_X2_T(r, addr) \
    asm volatile("ldmatrix.sync.aligned.m8n8.x2.trans.shared.b16 {%0,%1}, [%2];" \
                 : "=r"((r)[0]), "=r"((r)[1]) : "r"(addr))
#define MMA_BF16(c, a, b) \
    asm volatile("mma.sync.aligned.m16n8k16.row.col.f32.bf16.bf16.f32 " \
                 "{%0,%1,%2,%3}, {%4,%5,%6,%7}, {%8,%9}, {%0,%1,%2,%3};" \
                 : "+f"((c)[0]), "+f"((c)[1]), "+f"((c)[2]), "+f"((c)[3]) \
                 : "r"((a)[0]), "r"((a)[1]), "r"((a)[2]), "r"((a)[3]), \
                   "r"((b)[0]), "r"((b)[1]))

// ---------------- preprocessing kernels ----------------
__global__ void zero_degs_kernel() {
    int i = blockIdx.x * blockDim.x + threadIdx.x;
    if (i < N_NODES) { g_deg_src[i] = 0; g_deg_dst[i] = 0; }
}

// src/dst are int32 (JAX x64-disable downcasts the reference's int64 arrays).
__global__ void count_degs_kernel(const int* __restrict__ src,
                                  const int* __restrict__ dst) {
    int e = blockIdx.x * blockDim.x + threadIdx.x;
    if (e < N_EDGES) {
        atomicAdd(&g_deg_src[src[e]], 1);
        atomicAdd(&g_deg_dst[dst[e]], 1);
    }
}

__global__ void rsqrt_degs_kernel() {
    int i = blockIdx.x * blockDim.x + threadIdx.x;
    if (i < N_NODES) {
        int ds = g_deg_src[i]; if (ds < 1) ds = 1;
        int dd = g_deg_dst[i]; if (dd < 1) dd = 1;
        g_rs_src[i] = rsqrtf((float)ds);
        g_rs_dst[i] = rsqrtf((float)dd);
    }
}

__global__ void scan_block_sums_kernel() {
    __shared__ int sh[SCAN_B];
    int i = blockIdx.x * SCAN_B + threadIdx.x;
    sh[threadIdx.x] = (i < N_NODES) ? g_deg_dst[i] : 0;
    __syncthreads();
    #pragma unroll
    for (int s = SCAN_B / 2; s > 0; s >>= 1) {
        if (threadIdx.x < s) sh[threadIdx.x] += sh[threadIdx.x + s];
        __syncthreads();
    }
    if (threadIdx.x == 0) g_part[blockIdx.x] = sh[0];
}

__global__ void scan_partials_kernel() {
    if (blockIdx.x == 0 && threadIdx.x == 0) {
        int run = 0;
        for (int i = 0; i < NPART; ++i) { int t = g_part[i]; g_part[i] = run; run += t; }
        g_rowptr[N_NODES] = N_EDGES;
    }
}

__global__ void scan_final_kernel() {
    __shared__ int sh[SCAN_B];
    int tid = threadIdx.x;
    int i = blockIdx.x * SCAN_B + tid;
    int v = (i < N_NODES) ? g_deg_dst[i] : 0;
    sh[tid] = v;
    __syncthreads();
    #pragma unroll
    for (int off = 1; off < SCAN_B; off <<= 1) {
        int t = (tid >= off) ? sh[tid - off] : 0;
        __syncthreads();
        sh[tid] += t;
        __syncthreads();
    }
    if (i < N_NODES) {
        int excl = sh[tid] - v + g_part[blockIdx.x];
        g_rowptr[i] = excl;
        g_cursor[i] = excl;
    }
}

__global__ void fill_csr_kernel(const int* __restrict__ src,
                                const int* __restrict__ dst) {
    int e = blockIdx.x * blockDim.x + threadIdx.x;
    if (e < N_EDGES) {
        int pos = atomicAdd(&g_cursor[dst[e]], 1);
        g_col[pos] = src[e];
    }
}

__global__ void build_w_kernel(const float* __restrict__ W,
                               unsigned short* __restrict__ whi,
                               unsigned short* __restrict__ wlo) {
    int idx = blockIdx.x * blockDim.x + threadIdx.x;
    if (idx >= 128 * 128) return;
    float w = W[idx];
    __nv_bfloat16 hb = __float2bfloat16(w);
    __nv_bfloat16 lb = __float2bfloat16(w - __bfloat162float(hb));
    whi[idx] = __bfloat16_as_ushort(hb);
    wlo[idx] = __bfloat16_as_ushort(lb);
}

// Convert fp32 features -> fp16, pre-scaled by rs_src[row].
__global__ void conv_h16_kernel(const float* __restrict__ h) {
    size_t i = (size_t)blockIdx.x * blockDim.x + threadIdx.x;  // float4 index
    if (i >= (size_t)N_NODES * (F / 4)) return;
    int row = (int)(i >> 5);
    float rs = __ldg(&g_rs_src[row]);
    float4 v = __ldg(((const float4*)h) + i);
    *(__half2*)(g_h16a + i * 4)     = __floats2half2_rn(v.x * rs, v.y * rs);
    *(__half2*)(g_h16a + i * 4 + 2) = __floats2half2_rn(v.z * rs, v.w * rs);
}

// ---------------- fused aggregate + tensor-core GEMM ----------------
// Per CTA: aggregate 128 nodes' rows (fp16 gather, fp32 acc) straight into
// smem bf16 hi/lo A-tiles, then 3-pass split GEMM: D = Ah*Wh + Al*Wh + Ah*Wl.
// NOTE: hin and the output buffer must be DISTINCT (grid-wide WAR otherwise).
#define PADK 136
#define ROWB (PADK * 2)              // 272 bytes
#define TILE_BYTES (128 * ROWB)      // 34816
#define GEMM_SMEM_BYTES (4 * TILE_BYTES)  // 139264

template <int HALF_OUT>
__global__ void __launch_bounds__(256, 1)
fused_agg_gemm_kernel(const __half* __restrict__ hin,
                      const unsigned short* __restrict__ Whi,
                      const unsigned short* __restrict__ Wlo,
                      const float* __restrict__ bias,
                      float* __restrict__ out32,
                      __half* __restrict__ out16) {
    extern __shared__ __align__(16) unsigned char smem[];
    unsigned char* sAh = smem;
    unsigned char* sAl = smem + TILE_BYTES;
    unsigned char* sWh = smem + 2 * TILE_BYTES;
    unsigned char* sWl = smem + 3 * TILE_BYTES;

    int tid  = threadIdx.x;
    int wid  = tid >> 5;
    int lane = tid & 31;
    int row0 = blockIdx.x * 128;

    // ---- W tiles into padded smem (issue early; no sync needed until mainloop)
    {
        int r = tid >> 1, hf = tid & 1;
        const uint4* srch = (const uint4*)(Whi + r * 128 + hf * 64);
        const uint4* srcl = (const uint4*)(Wlo + r * 128 + hf * 64);
        uint4* dsth = (uint4*)(sWh + r * ROWB + hf * 128);
        uint4* dstl = (uint4*)(sWl + r * ROWB + hf * 128);
        #pragma unroll
        for (int i = 0; i < 8; ++i) { dsth[i] = __ldg(srch + i); dstl[i] = __ldg(srcl + i); }
    }

    // ---- Aggregate phase: warp handles 16 nodes; lane covers halves [lane*4, +4)
    {
        for (int nn = 0; nn < 16; ++nn) {
            int node = row0 + wid * 16 + nn;
            float a0 = 0.f, a1 = 0.f, a2 = 0.f, a3 = 0.f;
            if (node < N_NODES) {
                int beg = __ldg(&g_rowptr[node]);
                int end = __ldg(&g_rowptr[node + 1]);
                int e = beg;
                // 8 gathers in flight
                for (; e + 8 <= end; e += 8) {
                    int c0 = __ldg(&g_col[e]);
                    int c1 = __ldg(&g_col[e + 1]);
                    int c2 = __ldg(&g_col[e + 2]);
                    int c3 = __ldg(&g_col[e + 3]);
                    int c4 = __ldg(&g_col[e + 4]);
                    int c5 = __ldg(&g_col[e + 5]);
                    int c6 = __ldg(&g_col[e + 6]);
                    int c7 = __ldg(&g_col[e + 7]);
                    uint2 v0 = __ldg((const uint2*)(hin + (size_t)c0 * F + lane * 4));
                    uint2 v1 = __ldg((const uint2*)(hin + (size_t)c1 * F + lane * 4));
                    uint2 v2 = __ldg((const uint2*)(hin + (size_t)c2 * F + lane * 4));
                    uint2 v3 = __ldg((const uint2*)(hin + (size_t)c3 * F + lane * 4));
                    uint2 v4 = __ldg((const uint2*)(hin + (size_t)c4 * F + lane * 4));
                    uint2 v5 = __ldg((const uint2*)(hin + (size_t)c5 * F + lane * 4));
                    uint2 v6 = __ldg((const uint2*)(hin + (size_t)c6 * F + lane * 4));
                    uint2 v7 = __ldg((const uint2*)(hin + (size_t)c7 * F + lane * 4));
                    #define ACC8(v) do { \
                        float2 fa = __half22float2(*(const __half2*)&(v).x); \
                        float2 fb = __half22float2(*(const __half2*)&(v).y); \
                        a0 += fa.x; a1 += fa.y; a2 += fb.x; a3 += fb.y; } while (0)
                    ACC8(v0); ACC8(v1); ACC8(v2); ACC8(v3);
                    ACC8(v4); ACC8(v5); ACC8(v6); ACC8(v7);
                }
                for (; e < end; ++e) {
                    int c0 = __ldg(&g_col[e]);
                    uint2 v0 = __ldg((const uint2*)(hin + (size_t)c0 * F + lane * 4));
                    ACC8(v0);
                    #undef ACC8
                }
                float rd = __ldg(&g_rs_dst[node]);
                a0 *= rd; a1 *= rd; a2 *= rd; a3 *= rd;
            }
            // bf16 hi/lo split -> smem A tiles
            __nv_bfloat16 h0 = __float2bfloat16(a0), h1 = __float2bfloat16(a1);
            __nv_bfloat16 h2 = __float2bfloat16(a2), h3 = __float2bfloat16(a3);
            __nv_bfloat16 l0 = __float2bfloat16(a0 - __bfloat162float(h0));
            __nv_bfloat16 l1 = __float2bfloat16(a1 - __bfloat162float(h1));
            __nv_bfloat16 l2 = __float2bfloat16(a2 - __bfloat162float(h2));
            __nv_bfloat16 l3 = __float2bfloat16(a3 - __bfloat162float(h3));
            int r = wid * 16 + nn;
            uint2 ph = make_uint2(
                ((uint32_t)__bfloat16_as_ushort(h1) << 16) | __bfloat16_as_ushort(h0),
                ((uint32_t)__bfloat16_as_ushort(h3) << 16) | __bfloat16_as_ushort(h2));
            uint2 pl = make_uint2(
                ((uint32_t)__bfloat16_as_ushort(l1) << 16) | __bfloat16_as_ushort(l0),
                ((uint32_t)__bfloat16_as_ushort(l3) << 16) | __bfloat16_as_ushort(l2));
            *(uint2*)(sAh + r * ROWB + lane * 8) = ph;
            *(uint2*)(sAl + r * ROWB + lane * 8) = pl;
        }
    }
    __syncthreads();

    // ---- GEMM mainloop (3-pass bf16 split)
    int m0 = wid * 16;
    float acc[16][4];
    #pragma unroll
    for (int nt = 0; nt < 16; ++nt)
        #pragma unroll
        for (int c = 0; c < 4; ++c) acc[nt][c] = 0.f;

    uint32_t aoff = (uint32_t)(m0 + (lane & 15)) * ROWB + (uint32_t)(lane >> 4) * 16;
    uint32_t ah_base = smem_u32(sAh) + aoff;
    uint32_t al_base = smem_u32(sAl) + aoff;
    uint32_t wrow = (uint32_t)(lane & 15) * ROWB;
    uint32_t wh_base = smem_u32(sWh) + wrow;
    uint32_t wl_base = smem_u32(sWl) + wrow;

    #pragma unroll
    for (int ks = 0; ks < 8; ++ks) {
        uint32_t ah[4], al[4];
        LDSM_X4(ah, ah_base + ks * 32);
        LDSM_X4(al, al_base + ks * 32);
        uint32_t wh_k = wh_base + (uint32_t)ks * 16 * ROWB;
        uint32_t wl_k = wl_base + (uint32_t)ks * 16 * ROWB;
        #pragma unroll
        for (int nt = 0; nt < 16; ++nt) {
            uint32_t bh[2], bl[2];
            LDSM_X2_T(bh, wh_k + nt * 16);
            MMA_BF16(acc[nt], ah, bh);
            MMA_BF16(acc[nt], al, bh);
            LDSM_X2_T(bl, wl_k + nt * 16);
            MMA_BF16(acc[nt], ah, bl);
        }
    }

    // ---- Epilogue
    int r0 = row0 + m0 + (lane >> 2);
    int cb = 2 * (lane & 3);
    float rs0 = 0.f, rs1 = 0.f;
    if (HALF_OUT) {
        if (r0 < N_NODES)     rs0 = __ldg(&g_rs_src[r0]);
        if (r0 + 8 < N_NODES) rs1 = __ldg(&g_rs_src[r0 + 8]);
    }
    #pragma unroll
    for (int nt = 0; nt < 16; ++nt) {
        int n = nt * 8 + cb;
        float bx = __ldg(&bias[n]), by = __ldg(&bias[n + 1]);
        float v0x = fmaxf(acc[nt][0] + bx, 0.f);
        float v0y = fmaxf(acc[nt][1] + by, 0.f);
        float v1x = fmaxf(acc[nt][2] + bx, 0.f);
        float v1y = fmaxf(acc[nt][3] + by, 0.f);
        if (HALF_OUT) {
            if (r0 < N_NODES)
                *(__half2*)(out16 + (size_t)r0 * F + n) = __floats2half2_rn(v0x * rs0, v0y * rs0);
            if (r0 + 8 < N_NODES)
                *(__half2*)(out16 + (size_t)(r0 + 8) * F + n) = __floats2half2_rn(v1x * rs1, v1y * rs1);
        } else {
            if (r0 < N_NODES)
                *(float2*)(out32 + (size_t)r0 * F + n) = make_float2(v0x, v0y);
            if (r0 + 8 < N_NODES)
                *(float2*)(out32 + (size_t)(r0 + 8) * F + n) = make_float2(v1x, v1y);
        }
    }
}

// ---------------- host launch ----------------
extern "C" void kernel_launch(void* const* d_in, const int* in_sizes, int n_in,
                              void* d_out, int out_size) {
    const float* features = (const float*)d_in[0];
    const float* W1       = (const float*)d_in[1];
    const float* b1       = (const float*)d_in[2];
    const float* W2       = (const float*)d_in[3];
    const float* b2       = (const float*)d_in[4];
    const int*   src      = (const int*)d_in[5];
    const int*   dst      = (const int*)d_in[6];
    float*       out      = (float*)d_out;

    __half *h16a = nullptr, *h16b = nullptr;
    unsigned short *whi = nullptr, *wlo = nullptr;
    cudaGetSymbolAddress((void**)&h16a, g_h16a);
    cudaGetSymbolAddress((void**)&h16b, g_h16b);
    cudaGetSymbolAddress((void**)&whi, g_Whi);
    cudaGetSymbolAddress((void**)&wlo, g_Wlo);

    cudaFuncSetAttribute(fused_agg_gemm_kernel<0>,
                         cudaFuncAttributeMaxDynamicSharedMemorySize, GEMM_SMEM_BYTES);
    cudaFuncSetAttribute(fused_agg_gemm_kernel<1>,
                         cudaFuncAttributeMaxDynamicSharedMemorySize, GEMM_SMEM_BYTES);

    int nblk_nodes = (N_NODES + 255) / 256;
    int nblk_edges = (N_EDGES + 255) / 256;
    int nblk_conv  = (int)(((size_t)N_NODES * (F / 4) + 255) / 256);
    int nblk_gemm  = (N_NODES + 127) / 128;        // 782

    // Preprocessing (deterministic each call)
    zero_degs_kernel<<<nblk_nodes, 256>>>();
    count_degs_kernel<<<nblk_edges, 256>>>(src, dst);
    rsqrt_degs_kernel<<<nblk_nodes, 256>>>();
    scan_block_sums_kernel<<<NPART, SCAN_B>>>();
    scan_partials_kernel<<<1, 32>>>();
    scan_final_kernel<<<NPART, SCAN_B>>>();
    fill_csr_kernel<<<nblk_edges, 256>>>(src, dst);
    build_w_kernel<<<64, 256>>>(W1, whi, wlo);
    build_w_kernel<<<64, 256>>>(W2, whi + 128 * 128, wlo + 128 * 128);

    // Layer 1: features -> h16a (rs_src-scaled); fused agg+GEMM reads h16a, writes h16b
    conv_h16_kernel<<<nblk_conv, 256>>>(features);
    fused_agg_gemm_kernel<1><<<nblk_gemm, 256, GEMM_SMEM_BYTES>>>(
        h16a, whi, wlo, b1, nullptr, h16b);

    // Layer 2: fused agg+GEMM reads h16b, writes fp32 out
    fused_agg_gemm_kernel<0><<<nblk_gemm, 256, GEMM_SMEM_BYTES>>>(
        h16b, whi + 128 * 128, wlo + 128 * 128, b2, out, nullptr);
}

// round 10
// speedup vs baseline: 1.6423x; 1.6423x over previous
#include <cuda_runtime.h>
#include <cuda_bf16.h>
#include <cuda_fp16.h>
#include <cstdint>

#define N_NODES 100000
#define N_EDGES 1600000
#define F 128
#define SCAN_B 1024
#define NPART ((N_NODES + SCAN_B - 1) / SCAN_B)   // 98

// ---------------- device scratch (allocation-free rule) ----------------
__device__ __align__(16) float  g_agg[(size_t)N_NODES * F];  // 51.2 MB
__device__ __align__(16) __half g_h16[(size_t)N_NODES * F];  // 25.6 MB
__device__ int   g_deg_src[N_NODES];
__device__ int   g_deg_dst[N_NODES];
__device__ float g_rs_src[N_NODES];
__device__ float g_rs_dst[N_NODES];
__device__ int   g_rowptr[N_NODES + 1];
__device__ int   g_cursor[N_NODES];
__device__ int   g_col[N_EDGES];                  // 6.4 MB
__device__ int   g_part[NPART];
__device__ __align__(16) unsigned short g_Whi[2][128 * 128];
__device__ __align__(16) unsigned short g_Wlo[2][128 * 128];

// ---------------- mma.sync helpers ----------------
__device__ __forceinline__ uint32_t smem_u32(const void* p) {
    uint32_t a;
    asm("{ .reg .u64 t; cvta.to.shared.u64 t, %1; cvt.u32.u64 %0, t; }"
        : "=r"(a) : "l"(p));
    return a;
}
#define LDSM_X4(r, addr) \
    asm volatile("ldmatrix.sync.aligned.m8n8.x4.shared.b16 {%0,%1,%2,%3}, [%4];" \
                 : "=r"((r)[0]), "=r"((r)[1]), "=r"((r)[2]), "=r"((r)[3]) \
                 : "r"(addr))
#define LDSM_X2_T(r, addr) \
    asm volatile("ldmatrix.sync.aligned.m8n8.x2.trans.shared.b16 {%0,%1}, [%2];" \
                 : "=r"((r)[0]), "=r"((r)[1]) : "r"(addr))
#define MMA_BF16(c, a, b) \
    asm volatile("mma.sync.aligned.m16n8k16.row.col.f32.bf16.bf16.f32 " \
                 "{%0,%1,%2,%3}, {%4,%5,%6,%7}, {%8,%9}, {%0,%1,%2,%3};" \
                 : "+f"((c)[0]), "+f"((c)[1]), "+f"((c)[2]), "+f"((c)[3]) \
                 : "r"((a)[0]), "r"((a)[1]), "r"((a)[2]), "r"((a)[3]), \
                   "r"((b)[0]), "r"((b)[1]))

// ---------------- preprocessing kernels ----------------
__global__ void zero_degs_kernel() {
    int i = blockIdx.x * blockDim.x + threadIdx.x;
    if (i < N_NODES) { g_deg_src[i] = 0; g_deg_dst[i] = 0; }
}

// src/dst are int32 (JAX x64-disable downcasts the reference's int64 arrays).
__global__ void count_degs_kernel(const int* __restrict__ src,
                                  const int* __restrict__ dst) {
    int e = blockIdx.x * blockDim.x + threadIdx.x;
    if (e < N_EDGES) {
        atomicAdd(&g_deg_src[src[e]], 1);
        atomicAdd(&g_deg_dst[dst[e]], 1);
    }
}

__global__ void rsqrt_degs_kernel() {
    int i = blockIdx.x * blockDim.x + threadIdx.x;
    if (i < N_NODES) {
        int ds = g_deg_src[i]; if (ds < 1) ds = 1;
        int dd = g_deg_dst[i]; if (dd < 1) dd = 1;
        g_rs_src[i] = rsqrtf((float)ds);
        g_rs_dst[i] = rsqrtf((float)dd);
    }
}

__global__ void scan_block_sums_kernel() {
    __shared__ int sh[SCAN_B];
    int i = blockIdx.x * SCAN_B + threadIdx.x;
    sh[threadIdx.x] = (i < N_NODES) ? g_deg_dst[i] : 0;
    __syncthreads();
    #pragma unroll
    for (int s = SCAN_B / 2; s > 0; s >>= 1) {
        if (threadIdx.x < s) sh[threadIdx.x] += sh[threadIdx.x + s];
        __syncthreads();
    }
    if (threadIdx.x == 0) g_part[blockIdx.x] = sh[0];
}

__global__ void scan_partials_kernel() {
    if (blockIdx.x == 0 && threadIdx.x == 0) {
        int run = 0;
        for (int i = 0; i < NPART; ++i) { int t = g_part[i]; g_part[i] = run; run += t; }
        g_rowptr[N_NODES] = N_EDGES;
    }
}

__global__ void scan_final_kernel() {
    __shared__ int sh[SCAN_B];
    int tid = threadIdx.x;
    int i = blockIdx.x * SCAN_B + tid;
    int v = (i < N_NODES) ? g_deg_dst[i] : 0;
    sh[tid] = v;
    __syncthreads();
    #pragma unroll
    for (int off = 1; off < SCAN_B; off <<= 1) {
        int t = (tid >= off) ? sh[tid - off] : 0;
        __syncthreads();
        sh[tid] += t;
        __syncthreads();
    }
    if (i < N_NODES) {
        int excl = sh[tid] - v + g_part[blockIdx.x];
        g_rowptr[i] = excl;
        g_cursor[i] = excl;
    }
}

__global__ void fill_csr_kernel(const int* __restrict__ src,
                                const int* __restrict__ dst) {
    int e = blockIdx.x * blockDim.x + threadIdx.x;
    if (e < N_EDGES) {
        int pos = atomicAdd(&g_cursor[dst[e]], 1);
        g_col[pos] = src[e];
    }
}

__global__ void build_w_kernel(const float* __restrict__ W,
                               unsigned short* __restrict__ whi,
                               unsigned short* __restrict__ wlo) {
    int idx = blockIdx.x * blockDim.x + threadIdx.x;
    if (idx >= 128 * 128) return;
    float w = W[idx];
    __nv_bfloat16 hb = __float2bfloat16(w);
    __nv_bfloat16 lb = __float2bfloat16(w - __bfloat162float(hb));
    whi[idx] = __bfloat16_as_ushort(hb);
    wlo[idx] = __bfloat16_as_ushort(lb);
}

// Convert fp32 features -> fp16, pre-scaled by rs_src[row].
__global__ void conv_h16_kernel(const float* __restrict__ h) {
    size_t i = (size_t)blockIdx.x * blockDim.x + threadIdx.x;  // float4 index
    if (i >= (size_t)N_NODES * (F / 4)) return;
    int row = (int)(i >> 5);
    float rs = __ldg(&g_rs_src[row]);
    float4 v = __ldg(((const float4*)h) + i);
    *(__half2*)(g_h16 + i * 4)     = __floats2half2_rn(v.x * rs, v.y * rs);
    *(__half2*)(g_h16 + i * 4 + 2) = __floats2half2_rn(v.z * rs, v.w * rs);
}

// ---------------- aggregation: one warp per node, 8-deep gather MLP -------
// agg[n,:] = rs_dst[n] * sum_{s in N_in(n)} h16[s,:]   (h16 pre-scaled by rs_src)
// Lane covers halves [lane*4, lane*4+4) (8 B uint2); 8 edges in flight.
__global__ void __launch_bounds__(256)
aggregate16_kernel(float* __restrict__ out) {
    int node = (blockIdx.x * blockDim.x + threadIdx.x) >> 5;
    int lane = threadIdx.x & 31;
    if (node >= N_NODES) return;

    int beg = __ldg(&g_rowptr[node]);
    int end = __ldg(&g_rowptr[node + 1]);

    float a0 = 0.f, a1 = 0.f, a2 = 0.f, a3 = 0.f;
    int e = beg;
    for (; e + 8 <= end; e += 8) {
        int c0 = __ldg(&g_col[e]);
        int c1 = __ldg(&g_col[e + 1]);
        int c2 = __ldg(&g_col[e + 2]);
        int c3 = __ldg(&g_col[e + 3]);
        int c4 = __ldg(&g_col[e + 4]);
        int c5 = __ldg(&g_col[e + 5]);
        int c6 = __ldg(&g_col[e + 6]);
        int c7 = __ldg(&g_col[e + 7]);
        uint2 v0 = __ldg((const uint2*)(g_h16 + (size_t)c0 * F + lane * 4));
        uint2 v1 = __ldg((const uint2*)(g_h16 + (size_t)c1 * F + lane * 4));
        uint2 v2 = __ldg((const uint2*)(g_h16 + (size_t)c2 * F + lane * 4));
        uint2 v3 = __ldg((const uint2*)(g_h16 + (size_t)c3 * F + lane * 4));
        uint2 v4 = __ldg((const uint2*)(g_h16 + (size_t)c4 * F + lane * 4));
        uint2 v5 = __ldg((const uint2*)(g_h16 + (size_t)c5 * F + lane * 4));
        uint2 v6 = __ldg((const uint2*)(g_h16 + (size_t)c6 * F + lane * 4));
        uint2 v7 = __ldg((const uint2*)(g_h16 + (size_t)c7 * F + lane * 4));
        #define ACC(v) do { \
            float2 fa = __half22float2(*(const __half2*)&(v).x); \
            float2 fb = __half22float2(*(const __half2*)&(v).y); \
            a0 += fa.x; a1 += fa.y; a2 += fb.x; a3 += fb.y; } while (0)
        ACC(v0); ACC(v1); ACC(v2); ACC(v3);
        ACC(v4); ACC(v5); ACC(v6); ACC(v7);
    }
    for (; e < end; ++e) {
        int c0 = __ldg(&g_col[e]);
        uint2 v0 = __ldg((const uint2*)(g_h16 + (size_t)c0 * F + lane * 4));
        ACC(v0);
    }
    #undef ACC

    float rd = __ldg(&g_rs_dst[node]);
    float4 o = make_float4(a0 * rd, a1 * rd, a2 * rd, a3 * rd);
    *(float4*)(out + (size_t)node * F + lane * 4) = o;
}

// ---------------- tensor-core GEMM via mma.sync, 3-pass bf16 split -------
// D = Ah*Wh + Al*Wh + Ah*Wl (fp32 accum); relu(D + b).
// HALF_OUT=1: write __half pre-scaled by rs_src (feeds next aggregate).
#define PADK 136
#define ROWB (PADK * 2)              // 272 bytes
#define TILE_BYTES (128 * ROWB)      // 34816
#define GEMM_SMEM_BYTES (4 * TILE_BYTES)  // 139264

template <int HALF_OUT>
__global__ void __launch_bounds__(256, 1)
mma_gemm_kernel(const float* __restrict__ A,
                const unsigned short* __restrict__ Whi,
                const unsigned short* __restrict__ Wlo,
                const float* __restrict__ bias,
                float* __restrict__ out32,
                __half* __restrict__ out16) {
    extern __shared__ __align__(16) unsigned char smem[];
    unsigned char* sAh = smem;
    unsigned char* sAl = smem + TILE_BYTES;
    unsigned char* sWh = smem + 2 * TILE_BYTES;
    unsigned char* sWl = smem + 3 * TILE_BYTES;

    int tid  = threadIdx.x;
    int wid  = tid >> 5;
    int lane = tid & 31;
    int row0 = blockIdx.x * 128;

    {
        int r = tid >> 1, hf = tid & 1;
        const uint4* srch = (const uint4*)(Whi + r * 128 + hf * 64);
        const uint4* srcl = (const uint4*)(Wlo + r * 128 + hf * 64);
        uint4* dsth = (uint4*)(sWh + r * ROWB + hf * 128);
        uint4* dstl = (uint4*)(sWl + r * ROWB + hf * 128);
        #pragma unroll
        for (int i = 0; i < 8; ++i) { dsth[i] = __ldg(srch + i); dstl[i] = __ldg(srcl + i); }
    }
    {
        int r = tid >> 1, hf = tid & 1;
        int row = row0 + r;
        const float4* arow = (const float4*)(A + (size_t)row * F) + hf * 16;
        unsigned char* dh = sAh + r * ROWB + hf * 128;
        unsigned char* dl = sAl + r * ROWB + hf * 128;
        #pragma unroll
        for (int i = 0; i < 16; ++i) {
            float4 a = make_float4(0.f, 0.f, 0.f, 0.f);
            if (row < N_NODES) a = __ldg(arow + i);
            __nv_bfloat16 h0 = __float2bfloat16(a.x), h1 = __float2bfloat16(a.y);
            __nv_bfloat16 h2 = __float2bfloat16(a.z), h3 = __float2bfloat16(a.w);
            __nv_bfloat16 l0 = __float2bfloat16(a.x - __bfloat162float(h0));
            __nv_bfloat16 l1 = __float2bfloat16(a.y - __bfloat162float(h1));
            __nv_bfloat16 l2 = __float2bfloat16(a.z - __bfloat162float(h2));
            __nv_bfloat16 l3 = __float2bfloat16(a.w - __bfloat162float(h3));
            uint2 ph = make_uint2(
                ((uint32_t)__bfloat16_as_ushort(h1) << 16) | __bfloat16_as_ushort(h0),
                ((uint32_t)__bfloat16_as_ushort(h3) << 16) | __bfloat16_as_ushort(h2));
            uint2 pl = make_uint2(
                ((uint32_t)__bfloat16_as_ushort(l1) << 16) | __bfloat16_as_ushort(l0),
                ((uint32_t)__bfloat16_as_ushort(l3) << 16) | __bfloat16_as_ushort(l2));
            *(uint2*)(dh + i * 8) = ph;
            *(uint2*)(dl + i * 8) = pl;
        }
    }
    __syncthreads();

    int m0 = wid * 16;
    float acc[16][4];
    #pragma unroll
    for (int nt = 0; nt < 16; ++nt)
        #pragma unroll
        for (int c = 0; c < 4; ++c) acc[nt][c] = 0.f;

    uint32_t aoff = (uint32_t)(m0 + (lane & 15)) * ROWB + (uint32_t)(lane >> 4) * 16;
    uint32_t ah_base = smem_u32(sAh) + aoff;
    uint32_t al_base = smem_u32(sAl) + aoff;
    uint32_t wrow = (uint32_t)(lane & 15) * ROWB;
    uint32_t wh_base = smem_u32(sWh) + wrow;
    uint32_t wl_base = smem_u32(sWl) + wrow;

    #pragma unroll
    for (int ks = 0; ks < 8; ++ks) {
        uint32_t ah[4], al[4];
        LDSM_X4(ah, ah_base + ks * 32);
        LDSM_X4(al, al_base + ks * 32);
        uint32_t wh_k = wh_base + (uint32_t)ks * 16 * ROWB;
        uint32_t wl_k = wl_base + (uint32_t)ks * 16 * ROWB;
        #pragma unroll
        for (int nt = 0; nt < 16; ++nt) {
            uint32_t bh[2], bl[2];
            LDSM_X2_T(bh, wh_k + nt * 16);
            MMA_BF16(acc[nt], ah, bh);
            MMA_BF16(acc[nt], al, bh);
            LDSM_X2_T(bl, wl_k + nt * 16);
            MMA_BF16(acc[nt], ah, bl);
        }
    }

    int r0 = row0 + m0 + (lane >> 2);
    int cb = 2 * (lane & 3);
    float rs0 = 0.f, rs1 = 0.f;
    if (HALF_OUT) {
        if (r0 < N_NODES)     rs0 = __ldg(&g_rs_src[r0]);
        if (r0 + 8 < N_NODES) rs1 = __ldg(&g_rs_src[r0 + 8]);
    }
    #pragma unroll
    for (int nt = 0; nt < 16; ++nt) {
        int n = nt * 8 + cb;
        float bx = __ldg(&bias[n]), by = __ldg(&bias[n + 1]);
        float v0x = fmaxf(acc[nt][0] + bx, 0.f);
        float v0y = fmaxf(acc[nt][1] + by, 0.f);
        float v1x = fmaxf(acc[nt][2] + bx, 0.f);
        float v1y = fmaxf(acc[nt][3] + by, 0.f);
        if (HALF_OUT) {
            if (r0 < N_NODES)
                *(__half2*)(out16 + (size_t)r0 * F + n) = __floats2half2_rn(v0x * rs0, v0y * rs0);
            if (r0 + 8 < N_NODES)
                *(__half2*)(out16 + (size_t)(r0 + 8) * F + n) = __floats2half2_rn(v1x * rs1, v1y * rs1);
        } else {
            if (r0 < N_NODES)
                *(float2*)(out32 + (size_t)r0 * F + n) = make_float2(v0x, v0y);
            if (r0 + 8 < N_NODES)
                *(float2*)(out32 + (size_t)(r0 + 8) * F + n) = make_float2(v1x, v1y);
        }
    }
}

// ---------------- host launch ----------------
extern "C" void kernel_launch(void* const* d_in, const int* in_sizes, int n_in,
                              void* d_out, int out_size) {
    const float* features = (const float*)d_in[0];
    const float* W1       = (const float*)d_in[1];
    const float* b1       = (const float*)d_in[2];
    const float* W2       = (const float*)d_in[3];
    const float* b2       = (const float*)d_in[4];
    const int*   src      = (const int*)d_in[5];
    const int*   dst      = (const int*)d_in[6];
    float*       out      = (float*)d_out;

    float *agg = nullptr;
    __half *h16 = nullptr;
    unsigned short *whi = nullptr, *wlo = nullptr;
    cudaGetSymbolAddress((void**)&agg, g_agg);
    cudaGetSymbolAddress((void**)&h16, g_h16);
    cudaGetSymbolAddress((void**)&whi, g_Whi);
    cudaGetSymbolAddress((void**)&wlo, g_Wlo);

    cudaFuncSetAttribute(mma_gemm_kernel<0>,
                         cudaFuncAttributeMaxDynamicSharedMemorySize, GEMM_SMEM_BYTES);
    cudaFuncSetAttribute(mma_gemm_kernel<1>,
                         cudaFuncAttributeMaxDynamicSharedMemorySize, GEMM_SMEM_BYTES);

    int nblk_nodes = (N_NODES + 255) / 256;
    int nblk_edges = (N_EDGES + 255) / 256;
    int nblk_conv  = (int)(((size_t)N_NODES * (F / 4) + 255) / 256);
    int nblk_aggw  = (N_NODES * 32 + 255) / 256;   // one warp per node
    int nblk_gemm  = (N_NODES + 127) / 128;        // 782

    // Preprocessing (deterministic each call)
    zero_degs_kernel<<<nblk_nodes, 256>>>();
    count_degs_kernel<<<nblk_edges, 256>>>(src, dst);
    rsqrt_degs_kernel<<<nblk_nodes, 256>>>();
    scan_block_sums_kernel<<<NPART, SCAN_B>>>();
    scan_partials_kernel<<<1, 32>>>();
    scan_final_kernel<<<NPART, SCAN_B>>>();
    fill_csr_kernel<<<nblk_edges, 256>>>(src, dst);
    build_w_kernel<<<64, 256>>>(W1, whi, wlo);
    build_w_kernel<<<64, 256>>>(W2, whi + 128 * 128, wlo + 128 * 128);

    // Layer 1
    conv_h16_kernel<<<nblk_conv, 256>>>(features);
    aggregate16_kernel<<<nblk_aggw, 256>>>(agg);
    mma_gemm_kernel<1><<<nblk_gemm, 256, GEMM_SMEM_BYTES>>>(agg, whi, wlo, b1, nullptr, h16);

    // Layer 2
    aggregate16_kernel<<<nblk_aggw, 256>>>(agg);
    mma_gemm_kernel<0><<<nblk_gemm, 256, GEMM_SMEM_BYTES>>>(agg, whi + 128 * 128,
                                                            wlo + 128 * 128, b2, out, nullptr);
}

// round 11
// speedup vs baseline: 1.8066x; 1.1000x over previous
#include <cuda_runtime.h>
#include <cuda_fp16.h>
#include <cstdint>

#define N_NODES 100000
#define N_EDGES 1600000
#define F 128
#define SCAN_B 1024
#define NPART ((N_NODES + SCAN_B - 1) / SCAN_B)   // 98

// ---------------- device scratch (allocation-free rule) ----------------
__device__ __align__(16) float  g_agg[(size_t)N_NODES * F];  // 51.2 MB
__device__ __align__(16) __half g_h16[(size_t)N_NODES * F];  // 25.6 MB
__device__ int   g_deg_src[N_NODES];
__device__ int   g_deg_dst[N_NODES];
__device__ float g_rs_src[N_NODES];
__device__ float g_rs_dst[N_NODES];
__device__ int   g_rowptr[N_NODES + 1];
__device__ int   g_cursor[N_NODES];
__device__ int   g_col[N_EDGES];                  // 6.4 MB
__device__ int   g_part[NPART];
// W in fp16, natural [K=128][N=128] layout, 2 layers.
__device__ __align__(16) unsigned short g_Wh[2][128 * 128];

// ---------------- mma.sync helpers (portable PTX, sm_80+) ----------------
__device__ __forceinline__ uint32_t smem_u32(const void* p) {
    uint32_t a;
    asm("{ .reg .u64 t; cvta.to.shared.u64 t, %1; cvt.u32.u64 %0, t; }"
        : "=r"(a) : "l"(p));
    return a;
}
#define LDSM_X4(r, addr) \
    asm volatile("ldmatrix.sync.aligned.m8n8.x4.shared.b16 {%0,%1,%2,%3}, [%4];" \
                 : "=r"((r)[0]), "=r"((r)[1]), "=r"((r)[2]), "=r"((r)[3]) \
                 : "r"(addr))
#define LDSM_X2_T(r, addr) \
    asm volatile("ldmatrix.sync.aligned.m8n8.x2.trans.shared.b16 {%0,%1}, [%2];" \
                 : "=r"((r)[0]), "=r"((r)[1]) : "r"(addr))
#define MMA_FP16(c, a, b) \
    asm volatile("mma.sync.aligned.m16n8k16.row.col.f32.f16.f16.f32 " \
                 "{%0,%1,%2,%3}, {%4,%5,%6,%7}, {%8,%9}, {%0,%1,%2,%3};" \
                 : "+f"((c)[0]), "+f"((c)[1]), "+f"((c)[2]), "+f"((c)[3]) \
                 : "r"((a)[0]), "r"((a)[1]), "r"((a)[2]), "r"((a)[3]), \
                   "r"((b)[0]), "r"((b)[1]))

// ---------------- preprocessing kernels ----------------
__global__ void zero_degs_kernel() {
    int i = blockIdx.x * blockDim.x + threadIdx.x;
    if (i < N_NODES) { g_deg_src[i] = 0; g_deg_dst[i] = 0; }
}

// src/dst are int32 (JAX x64-disable downcasts the reference's int64 arrays).
__global__ void count_degs_kernel(const int* __restrict__ src,
                                  const int* __restrict__ dst) {
    int e = blockIdx.x * blockDim.x + threadIdx.x;
    if (e < N_EDGES) {
        atomicAdd(&g_deg_src[src[e]], 1);
        atomicAdd(&g_deg_dst[dst[e]], 1);
    }
}

__global__ void scan_block_sums_kernel() {
    __shared__ int sh[SCAN_B];
    int i = blockIdx.x * SCAN_B + threadIdx.x;
    sh[threadIdx.x] = (i < N_NODES) ? g_deg_dst[i] : 0;
    __syncthreads();
    #pragma unroll
    for (int s = SCAN_B / 2; s > 0; s >>= 1) {
        if (threadIdx.x < s) sh[threadIdx.x] += sh[threadIdx.x + s];
        __syncthreads();
    }
    if (threadIdx.x == 0) g_part[blockIdx.x] = sh[0];
}

__global__ void scan_partials_kernel() {
    if (blockIdx.x == 0 && threadIdx.x == 0) {
        int run = 0;
        for (int i = 0; i < NPART; ++i) { int t = g_part[i]; g_part[i] = run; run += t; }
        g_rowptr[N_NODES] = N_EDGES;
    }
}

// Final scan pass; also computes rs_src/rs_dst (folded from rsqrt_degs).
__global__ void scan_final_kernel() {
    __shared__ int sh[SCAN_B];
    int tid = threadIdx.x;
    int i = blockIdx.x * SCAN_B + tid;
    int v = (i < N_NODES) ? g_deg_dst[i] : 0;
    sh[tid] = v;
    __syncthreads();
    #pragma unroll
    for (int off = 1; off < SCAN_B; off <<= 1) {
        int t = (tid >= off) ? sh[tid - off] : 0;
        __syncthreads();
        sh[tid] += t;
        __syncthreads();
    }
    if (i < N_NODES) {
        int excl = sh[tid] - v + g_part[blockIdx.x];
        g_rowptr[i] = excl;
        g_cursor[i] = excl;
        int ds = g_deg_src[i]; if (ds < 1) ds = 1;
        int dd = v; if (dd < 1) dd = 1;
        g_rs_src[i] = rsqrtf((float)ds);
        g_rs_dst[i] = rsqrtf((float)dd);
    }
}

__global__ void fill_csr_kernel(const int* __restrict__ src,
                                const int* __restrict__ dst) {
    int e = blockIdx.x * blockDim.x + threadIdx.x;
    if (e < N_EDGES) {
        int pos = atomicAdd(&g_cursor[dst[e]], 1);
        g_col[pos] = src[e];
    }
}

// W[k][n] fp32 -> fp16 (single), same layout.
__global__ void build_w_kernel(const float* __restrict__ W,
                               unsigned short* __restrict__ wh) {
    int idx = blockIdx.x * blockDim.x + threadIdx.x;
    if (idx >= 128 * 128) return;
    __half h = __float2half_rn(W[idx]);
    wh[idx] = __half_as_ushort(h);
}

// Convert fp32 features -> fp16, pre-scaled by rs_src[row].
__global__ void conv_h16_kernel(const float* __restrict__ h) {
    size_t i = (size_t)blockIdx.x * blockDim.x + threadIdx.x;  // float4 index
    if (i >= (size_t)N_NODES * (F / 4)) return;
    int row = (int)(i >> 5);
    float rs = __ldg(&g_rs_src[row]);
    float4 v = __ldg(((const float4*)h) + i);
    *(__half2*)(g_h16 + i * 4)     = __floats2half2_rn(v.x * rs, v.y * rs);
    *(__half2*)(g_h16 + i * 4 + 2) = __floats2half2_rn(v.z * rs, v.w * rs);
}

// ---------------- aggregation (R10, passing at 289.6us) ----------------
__global__ void __launch_bounds__(256)
aggregate16_kernel(float* __restrict__ out) {
    int node = (blockIdx.x * blockDim.x + threadIdx.x) >> 5;
    int lane = threadIdx.x & 31;
    if (node >= N_NODES) return;

    int beg = __ldg(&g_rowptr[node]);
    int end = __ldg(&g_rowptr[node + 1]);

    float a0 = 0.f, a1 = 0.f, a2 = 0.f, a3 = 0.f;
    int e = beg;
    for (; e + 8 <= end; e += 8) {
        int c0 = __ldg(&g_col[e]);
        int c1 = __ldg(&g_col[e + 1]);
        int c2 = __ldg(&g_col[e + 2]);
        int c3 = __ldg(&g_col[e + 3]);
        int c4 = __ldg(&g_col[e + 4]);
        int c5 = __ldg(&g_col[e + 5]);
        int c6 = __ldg(&g_col[e + 6]);
        int c7 = __ldg(&g_col[e + 7]);
        uint2 v0 = __ldg((const uint2*)(g_h16 + (size_t)c0 * F + lane * 4));
        uint2 v1 = __ldg((const uint2*)(g_h16 + (size_t)c1 * F + lane * 4));
        uint2 v2 = __ldg((const uint2*)(g_h16 + (size_t)c2 * F + lane * 4));
        uint2 v3 = __ldg((const uint2*)(g_h16 + (size_t)c3 * F + lane * 4));
        uint2 v4 = __ldg((const uint2*)(g_h16 + (size_t)c4 * F + lane * 4));
        uint2 v5 = __ldg((const uint2*)(g_h16 + (size_t)c5 * F + lane * 4));
        uint2 v6 = __ldg((const uint2*)(g_h16 + (size_t)c6 * F + lane * 4));
        uint2 v7 = __ldg((const uint2*)(g_h16 + (size_t)c7 * F + lane * 4));
        #define ACC(v) do { \
            float2 fa = __half22float2(*(const __half2*)&(v).x); \
            float2 fb = __half22float2(*(const __half2*)&(v).y); \
            a0 += fa.x; a1 += fa.y; a2 += fb.x; a3 += fb.y; } while (0)
        ACC(v0); ACC(v1); ACC(v2); ACC(v3);
        ACC(v4); ACC(v5); ACC(v6); ACC(v7);
    }
    for (; e < end; ++e) {
        int c0 = __ldg(&g_col[e]);
        uint2 v0 = __ldg((const uint2*)(g_h16 + (size_t)c0 * F + lane * 4));
        ACC(v0);
    }
    #undef ACC

    float rd = __ldg(&g_rs_dst[node]);
    float4 o = make_float4(a0 * rd, a1 * rd, a2 * rd, a3 * rd);
    *(float4*)(out + (size_t)node * F + lane * 4) = o;
}

// ---------------- tensor-core GEMM: 2-pass fp16 split -------------------
// D = Ah*Wh + Al*Wh (fp32 accum), A = Ah + Al in fp16 (~22-bit A), W fp16.
// 3 smem tiles (104 KB) -> 2 CTAs/SM.
#define PADK 136
#define ROWB (PADK * 2)              // 272 bytes
#define TILE_BYTES (128 * ROWB)      // 34816
#define GEMM_SMEM_BYTES (3 * TILE_BYTES)  // 104448

template <int HALF_OUT>
__global__ void __launch_bounds__(256, 2)
mma_gemm_kernel(const float* __restrict__ A,
                const unsigned short* __restrict__ Wh,
                const float* __restrict__ bias,
                float* __restrict__ out32,
                __half* __restrict__ out16) {
    extern __shared__ __align__(16) unsigned char smem[];
    unsigned char* sAh = smem;
    unsigned char* sAl = smem + TILE_BYTES;
    unsigned char* sWh = smem + 2 * TILE_BYTES;

    int tid  = threadIdx.x;
    int wid  = tid >> 5;
    int lane = tid & 31;
    int row0 = blockIdx.x * 128;

    // ---- W tile into padded smem
    {
        int r = tid >> 1, hf = tid & 1;
        const uint4* srch = (const uint4*)(Wh + r * 128 + hf * 64);
        uint4* dsth = (uint4*)(sWh + r * ROWB + hf * 128);
        #pragma unroll
        for (int i = 0; i < 8; ++i) dsth[i] = __ldg(srch + i);
    }
    // ---- A tile fp32 -> fp16 hi/lo split into padded smem
    {
        int r = tid >> 1, hf = tid & 1;
        int row = row0 + r;
        const float4* arow = (const float4*)(A + (size_t)row * F) + hf * 16;
        unsigned char* dh = sAh + r * ROWB + hf * 128;
        unsigned char* dl = sAl + r * ROWB + hf * 128;
        #pragma unroll
        for (int i = 0; i < 16; ++i) {
            float4 a = make_float4(0.f, 0.f, 0.f, 0.f);
            if (row < N_NODES) a = __ldg(arow + i);
            __half h0 = __float2half_rn(a.x), h1 = __float2half_rn(a.y);
            __half h2 = __float2half_rn(a.z), h3 = __float2half_rn(a.w);
            __half l0 = __float2half_rn(a.x - __half2float(h0));
            __half l1 = __float2half_rn(a.y - __half2float(h1));
            __half l2 = __float2half_rn(a.z - __half2float(h2));
            __half l3 = __float2half_rn(a.w - __half2float(h3));
            uint2 ph = make_uint2(
                ((uint32_t)__half_as_ushort(h1) << 16) | __half_as_ushort(h0),
                ((uint32_t)__half_as_ushort(h3) << 16) | __half_as_ushort(h2));
            uint2 pl = make_uint2(
                ((uint32_t)__half_as_ushort(l1) << 16) | __half_as_ushort(l0),
                ((uint32_t)__half_as_ushort(l3) << 16) | __half_as_ushort(l2));
            *(uint2*)(dh + i * 8) = ph;
            *(uint2*)(dl + i * 8) = pl;
        }
    }
    __syncthreads();

    int m0 = wid * 16;
    float acc[16][4];
    #pragma unroll
    for (int nt = 0; nt < 16; ++nt)
        #pragma unroll
        for (int c = 0; c < 4; ++c) acc[nt][c] = 0.f;

    uint32_t aoff = (uint32_t)(m0 + (lane & 15)) * ROWB + (uint32_t)(lane >> 4) * 16;
    uint32_t ah_base = smem_u32(sAh) + aoff;
    uint32_t al_base = smem_u32(sAl) + aoff;
    uint32_t wrow = (uint32_t)(lane & 15) * ROWB;
    uint32_t wh_base = smem_u32(sWh) + wrow;

    #pragma unroll
    for (int ks = 0; ks < 8; ++ks) {
        uint32_t ah[4], al[4];
        LDSM_X4(ah, ah_base + ks * 32);
        LDSM_X4(al, al_base + ks * 32);
        uint32_t wh_k = wh_base + (uint32_t)ks * 16 * ROWB;
        #pragma unroll
        for (int nt = 0; nt < 16; ++nt) {
            uint32_t bh[2];
            LDSM_X2_T(bh, wh_k + nt * 16);
            MMA_FP16(acc[nt], ah, bh);
            MMA_FP16(acc[nt], al, bh);
        }
    }

    // ---- Epilogue
    int r0 = row0 + m0 + (lane >> 2);
    int cb = 2 * (lane & 3);
    float rs0 = 0.f, rs1 = 0.f;
    if (HALF_OUT) {
        if (r0 < N_NODES)     rs0 = __ldg(&g_rs_src[r0]);
        if (r0 + 8 < N_NODES) rs1 = __ldg(&g_rs_src[r0 + 8]);
    }
    #pragma unroll
    for (int nt = 0; nt < 16; ++nt) {
        int n = nt * 8 + cb;
        float bx = __ldg(&bias[n]), by = __ldg(&bias[n + 1]);
        float v0x = fmaxf(acc[nt][0] + bx, 0.f);
        float v0y = fmaxf(acc[nt][1] + by, 0.f);
        float v1x = fmaxf(acc[nt][2] + bx, 0.f);
        float v1y = fmaxf(acc[nt][3] + by, 0.f);
        if (HALF_OUT) {
            if (r0 < N_NODES)
                *(__half2*)(out16 + (size_t)r0 * F + n) = __floats2half2_rn(v0x * rs0, v0y * rs0);
            if (r0 + 8 < N_NODES)
                *(__half2*)(out16 + (size_t)(r0 + 8) * F + n) = __floats2half2_rn(v1x * rs1, v1y * rs1);
        } else {
            if (r0 < N_NODES)
                *(float2*)(out32 + (size_t)r0 * F + n) = make_float2(v0x, v0y);
            if (r0 + 8 < N_NODES)
                *(float2*)(out32 + (size_t)(r0 + 8) * F + n) = make_float2(v1x, v1y);
        }
    }
}

// ---------------- host launch ----------------
extern "C" void kernel_launch(void* const* d_in, const int* in_sizes, int n_in,
                              void* d_out, int out_size) {
    const float* features = (const float*)d_in[0];
    const float* W1       = (const float*)d_in[1];
    const float* b1       = (const float*)d_in[2];
    const float* W2       = (const float*)d_in[3];
    const float* b2       = (const float*)d_in[4];
    const int*   src      = (const int*)d_in[5];
    const int*   dst      = (const int*)d_in[6];
    float*       out      = (float*)d_out;

    float *agg = nullptr;
    __half *h16 = nullptr;
    unsigned short *wh = nullptr;
    cudaGetSymbolAddress((void**)&agg, g_agg);
    cudaGetSymbolAddress((void**)&h16, g_h16);
    cudaGetSymbolAddress((void**)&wh,  g_Wh);

    cudaFuncSetAttribute(mma_gemm_kernel<0>,
                         cudaFuncAttributeMaxDynamicSharedMemorySize, GEMM_SMEM_BYTES);
    cudaFuncSetAttribute(mma_gemm_kernel<1>,
                         cudaFuncAttributeMaxDynamicSharedMemorySize, GEMM_SMEM_BYTES);

    int nblk_nodes = (N_NODES + 255) / 256;
    int nblk_edges = (N_EDGES + 255) / 256;
    int nblk_conv  = (int)(((size_t)N_NODES * (F / 4) + 255) / 256);
    int nblk_aggw  = (N_NODES * 32 + 255) / 256;   // one warp per node
    int nblk_gemm  = (N_NODES + 127) / 128;        // 782

    // Preprocessing (deterministic each call)
    zero_degs_kernel<<<nblk_nodes, 256>>>();
    count_degs_kernel<<<nblk_edges, 256>>>(src, dst);
    scan_block_sums_kernel<<<NPART, SCAN_B>>>();
    scan_partials_kernel<<<1, 32>>>();
    scan_final_kernel<<<NPART, SCAN_B>>>();       // also computes rs_src/rs_dst
    fill_csr_kernel<<<nblk_edges, 256>>>(src, dst);
    build_w_kernel<<<64, 256>>>(W1, wh);
    build_w_kernel<<<64, 256>>>(W2, wh + 128 * 128);

    // Layer 1
    conv_h16_kernel<<<nblk_conv, 256>>>(features);
    aggregate16_kernel<<<nblk_aggw, 256>>>(agg);
    mma_gemm_kernel<1><<<nblk_gemm, 256, GEMM_SMEM_BYTES>>>(agg, wh, b1, nullptr, h16);

    // Layer 2
    aggregate16_kernel<<<nblk_aggw, 256>>>(agg);
    mma_gemm_kernel<0><<<nblk_gemm, 256, GEMM_SMEM_BYTES>>>(agg, wh + 128 * 128, b2, out, nullptr);
}

// round 12
// speedup vs baseline: 2.3611x; 1.3069x over previous
#include <cuda_runtime.h>
#include <cuda_fp16.h>
#include <cstdint>

#define N_NODES 100000
#define N_EDGES 1600000
#define F 128
#define SCAN_B 1024
#define NPART ((N_NODES + SCAN_B - 1) / SCAN_B)   // 98
#define NB_NODES ((N_NODES + 255) / 256)          // 391
#define NB_EDGES ((N_EDGES + 255) / 256)          // 6250
#define NB_CONV  ((N_NODES * 32 + 255) / 256)     // 12500 (float4 elems)

// ---------------- device scratch (allocation-free rule) ----------------
__device__ __align__(16) __half g_h16[(size_t)N_NODES * F];  // 25.6 MB (features / h1)
__device__ __align__(16) __half g_a16[(size_t)N_NODES * F];  // 25.6 MB (aggregate out)
__device__ int   g_deg_src[N_NODES];
__device__ int   g_deg_dst[N_NODES];
__device__ float g_rs_src[N_NODES];
__device__ float g_rs_dst[N_NODES];
__device__ int   g_rowptr[N_NODES + 1];
__device__ int   g_cursor[N_NODES];
__device__ int   g_col[N_EDGES];                  // 6.4 MB
__device__ int   g_part[NPART];
__device__ __align__(16) unsigned short g_Wh[2][128 * 128];  // fp16 W

// ---------------- mma.sync helpers (portable PTX, sm_80+) ----------------
__device__ __forceinline__ uint32_t smem_u32(const void* p) {
    uint32_t a;
    asm("{ .reg .u64 t; cvta.to.shared.u64 t, %1; cvt.u32.u64 %0, t; }"
        : "=r"(a) : "l"(p));
    return a;
}
#define LDSM_X4(r, addr) \
    asm volatile("ldmatrix.sync.aligned.m8n8.x4.shared.b16 {%0,%1,%2,%3}, [%4];" \
                 : "=r"((r)[0]), "=r"((r)[1]), "=r"((r)[2]), "=r"((r)[3]) \
                 : "r"(addr))
#define LDSM_X4_T(r, addr) \
    asm volatile("ldmatrix.sync.aligned.m8n8.x4.trans.shared.b16 {%0,%1,%2,%3}, [%4];" \
                 : "=r"((r)[0]), "=r"((r)[1]), "=r"((r)[2]), "=r"((r)[3]) \
                 : "r"(addr))
#define MMA_FP16(c, a, b0, b1) \
    asm volatile("mma.sync.aligned.m16n8k16.row.col.f32.f16.f16.f32 " \
                 "{%0,%1,%2,%3}, {%4,%5,%6,%7}, {%8,%9}, {%0,%1,%2,%3};" \
                 : "+f"((c)[0]), "+f"((c)[1]), "+f"((c)[2]), "+f"((c)[3]) \
                 : "r"((a)[0]), "r"((a)[1]), "r"((a)[2]), "r"((a)[3]), \
                   "r"(b0), "r"(b1))

// ---------------- K1: zero degrees + build fp16 W (grid-partitioned) -----
__global__ void init_kernel(const float* __restrict__ W1,
                            const float* __restrict__ W2) {
    int b = blockIdx.x;
    int tid = threadIdx.x;
    if (b < NB_NODES) {
        int i = b * 256 + tid;
        if (i < N_NODES) { g_deg_src[i] = 0; g_deg_dst[i] = 0; }
    } else if (b < NB_NODES + 64) {
        int idx = (b - NB_NODES) * 256 + tid;          // 0..16383
        g_Wh[0][idx] = __half_as_ushort(__float2half_rn(W1[idx]));
    } else {
        int idx = (b - NB_NODES - 64) * 256 + tid;
        g_Wh[1][idx] = __half_as_ushort(__float2half_rn(W2[idx]));
    }
}

// K2: degree histogram. src/dst are int32 (JAX x64-disable downcasts int64).
__global__ void count_degs_kernel(const int* __restrict__ src,
                                  const int* __restrict__ dst) {
    int e = blockIdx.x * blockDim.x + threadIdx.x;
    if (e < N_EDGES) {
        atomicAdd(&g_deg_src[src[e]], 1);
        atomicAdd(&g_deg_dst[dst[e]], 1);
    }
}

// K3: per-block sums of deg_dst.
__global__ void scan_block_sums_kernel() {
    __shared__ int sh[SCAN_B];
    int i = blockIdx.x * SCAN_B + threadIdx.x;
    sh[threadIdx.x] = (i < N_NODES) ? g_deg_dst[i] : 0;
    __syncthreads();
    #pragma unroll
    for (int s = SCAN_B / 2; s > 0; s >>= 1) {
        if (threadIdx.x < s) sh[threadIdx.x] += sh[threadIdx.x + s];
        __syncthreads();
    }
    if (threadIdx.x == 0) g_part[blockIdx.x] = sh[0];
}

// K4: final scan. Each CTA self-computes its offset (sum of g_part[0..b)),
// then does an in-block inclusive scan; writes rowptr/cursor + rs factors.
__global__ void scan_final_kernel() {
    __shared__ int sh[SCAN_B];
    int tid = threadIdx.x;
    int b = blockIdx.x;
    int i = b * SCAN_B + tid;

    // block offset = sum of predecessor partials (b <= 97 < 1024)
    int partial = (tid < b) ? g_part[tid] : 0;
    sh[tid] = partial;
    __syncthreads();
    #pragma unroll
    for (int s = SCAN_B / 2; s > 0; s >>= 1) {
        if (tid < s) sh[tid] += sh[tid + s];
        __syncthreads();
    }
    int base = sh[0];
    __syncthreads();

    int v = (i < N_NODES) ? g_deg_dst[i] : 0;
    sh[tid] = v;
    __syncthreads();
    #pragma unroll
    for (int off = 1; off < SCAN_B; off <<= 1) {
        int t = (tid >= off) ? sh[tid - off] : 0;
        __syncthreads();
        sh[tid] += t;
        __syncthreads();
    }
    if (i < N_NODES) {
        int excl = sh[tid] - v + base;
        g_rowptr[i] = excl;
        g_cursor[i] = excl;
        int ds = g_deg_src[i]; if (ds < 1) ds = 1;
        int dd = v; if (dd < 1) dd = 1;
        g_rs_src[i] = rsqrtf((float)ds);
        g_rs_dst[i] = rsqrtf((float)dd);
    }
    if (b == NPART - 1 && tid == 0) g_rowptr[N_NODES] = N_EDGES;
}

// K5: fill CSR + convert features -> fp16 (rs_src-scaled), grid-partitioned.
__global__ void fill_conv_kernel(const int* __restrict__ src,
                                 const int* __restrict__ dst,
                                 const float* __restrict__ feat) {
    int b = blockIdx.x;
    int tid = threadIdx.x;
    if (b < NB_EDGES) {
        int e = b * 256 + tid;
        if (e < N_EDGES) {
            int pos = atomicAdd(&g_cursor[dst[e]], 1);
            g_col[pos] = src[e];
        }
    } else {
        size_t i = (size_t)(b - NB_EDGES) * 256 + tid;   // float4 index
        if (i < (size_t)N_NODES * (F / 4)) {
            int row = (int)(i >> 5);
            float rs = __ldg(&g_rs_src[row]);
            float4 v = __ldg(((const float4*)feat) + i);
            *(__half2*)(g_h16 + i * 4)     = __floats2half2_rn(v.x * rs, v.y * rs);
            *(__half2*)(g_h16 + i * 4 + 2) = __floats2half2_rn(v.z * rs, v.w * rs);
        }
    }
}

// ---------------- aggregation: one warp per node, fp16 in AND out --------
// out16[n,:] = fp16( rs_dst[n] * sum_{s in N_in(n)} hin[s,:] )
__global__ void __launch_bounds__(256)
aggregate16_kernel(const __half* __restrict__ hin, __half* __restrict__ out16) {
    int node = (blockIdx.x * blockDim.x + threadIdx.x) >> 5;
    int lane = threadIdx.x & 31;
    if (node >= N_NODES) return;

    int beg = __ldg(&g_rowptr[node]);
    int end = __ldg(&g_rowptr[node + 1]);

    float a0 = 0.f, a1 = 0.f, a2 = 0.f, a3 = 0.f;
    int e = beg;
    for (; e + 8 <= end; e += 8) {
        int c0 = __ldg(&g_col[e]);
        int c1 = __ldg(&g_col[e + 1]);
        int c2 = __ldg(&g_col[e + 2]);
        int c3 = __ldg(&g_col[e + 3]);
        int c4 = __ldg(&g_col[e + 4]);
        int c5 = __ldg(&g_col[e + 5]);
        int c6 = __ldg(&g_col[e + 6]);
        int c7 = __ldg(&g_col[e + 7]);
        uint2 v0 = __ldg((const uint2*)(hin + (size_t)c0 * F + lane * 4));
        uint2 v1 = __ldg((const uint2*)(hin + (size_t)c1 * F + lane * 4));
        uint2 v2 = __ldg((const uint2*)(hin + (size_t)c2 * F + lane * 4));
        uint2 v3 = __ldg((const uint2*)(hin + (size_t)c3 * F + lane * 4));
        uint2 v4 = __ldg((const uint2*)(hin + (size_t)c4 * F + lane * 4));
        uint2 v5 = __ldg((const uint2*)(hin + (size_t)c5 * F + lane * 4));
        uint2 v6 = __ldg((const uint2*)(hin + (size_t)c6 * F + lane * 4));
        uint2 v7 = __ldg((const uint2*)(hin + (size_t)c7 * F + lane * 4));
        #define ACC(v) do { \
            float2 fa = __half22float2(*(const __half2*)&(v).x); \
            float2 fb = __half22float2(*(const __half2*)&(v).y); \
            a0 += fa.x; a1 += fa.y; a2 += fb.x; a3 += fb.y; } while (0)
        ACC(v0); ACC(v1); ACC(v2); ACC(v3);
        ACC(v4); ACC(v5); ACC(v6); ACC(v7);
    }
    for (; e < end; ++e) {
        int c0 = __ldg(&g_col[e]);
        uint2 v0 = __ldg((const uint2*)(hin + (size_t)c0 * F + lane * 4));
        ACC(v0);
    }
    #undef ACC

    float rd = __ldg(&g_rs_dst[node]);
    uint2 o;
    *(__half2*)&o.x = __floats2half2_rn(a0 * rd, a1 * rd);
    *(__half2*)&o.y = __floats2half2_rn(a2 * rd, a3 * rd);
    *(uint2*)(out16 + (size_t)node * F + lane * 4) = o;
}

// ---------------- tensor-core GEMM: single-pass fp16 ---------------------
// D = A16 * W16 (fp32 accum); relu(D + b). A already fp16 (aggregate out).
// 2 smem tiles (68 KB) -> 2 CTAs/SM. W fragments via ldmatrix.x4.trans.
#define PADK 136
#define ROWB (PADK * 2)              // 272 bytes
#define TILE_BYTES (128 * ROWB)      // 34816
#define GEMM_SMEM_BYTES (2 * TILE_BYTES)  // 69632

template <int HALF_OUT>
__global__ void __launch_bounds__(256, 2)
mma_gemm_kernel(const __half* __restrict__ A16,
                const unsigned short* __restrict__ Wh,
                const float* __restrict__ bias,
                float* __restrict__ out32,
                __half* __restrict__ out16) {
    extern __shared__ __align__(16) unsigned char smem[];
    unsigned char* sA = smem;
    unsigned char* sW = smem + TILE_BYTES;

    int tid  = threadIdx.x;
    int wid  = tid >> 5;
    int lane = tid & 31;
    int row0 = blockIdx.x * 128;

    // ---- W tile into padded smem (raw copy, fp16)
    {
        int r = tid >> 1, hf = tid & 1;
        const uint4* srcw = (const uint4*)(Wh + r * 128 + hf * 64);
        uint4* dstw = (uint4*)(sW + r * ROWB + hf * 128);
        #pragma unroll
        for (int i = 0; i < 8; ++i) dstw[i] = __ldg(srcw + i);
    }
    // ---- A tile into padded smem (raw copy, fp16; zero-fill OOB rows)
    {
        int r = tid >> 1, hf = tid & 1;
        int row = row0 + r;
        uint4* dsta = (uint4*)(sA + r * ROWB + hf * 128);
        if (row < N_NODES) {
            const uint4* srca = (const uint4*)(A16 + (size_t)row * F + hf * 64);
            #pragma unroll
            for (int i = 0; i < 8; ++i) dsta[i] = __ldg(srca + i);
        } else {
            uint4 z = make_uint4(0, 0, 0, 0);
            #pragma unroll
            for (int i = 0; i < 8; ++i) dsta[i] = z;
        }
    }
    __syncthreads();

    int m0 = wid * 16;
    float acc[16][4];
    #pragma unroll
    for (int nt = 0; nt < 16; ++nt)
        #pragma unroll
        for (int c = 0; c < 4; ++c) acc[nt][c] = 0.f;

    uint32_t aoff = (uint32_t)(m0 + (lane & 15)) * ROWB + (uint32_t)(lane >> 4) * 16;
    uint32_t a_base = smem_u32(sA) + aoff;
    // W x4.trans: lanes 0-15 -> k rows (col base), lanes 16-31 -> same rows, +16B (n+8)
    uint32_t wrow = (uint32_t)(lane & 15) * ROWB + (uint32_t)(lane >> 4) * 16;
    uint32_t w_base = smem_u32(sW) + wrow;

    #pragma unroll
    for (int ks = 0; ks < 8; ++ks) {
        uint32_t a[4];
        LDSM_X4(a, a_base + ks * 32);
        uint32_t w_k = w_base + (uint32_t)ks * 16 * ROWB;
        #pragma unroll
        for (int nt2 = 0; nt2 < 8; ++nt2) {
            uint32_t w[4];
            LDSM_X4_T(w, w_k + nt2 * 32);    // 2 B-fragments: n2*16 and n2*16+8
            MMA_FP16(acc[2 * nt2],     a, w[0], w[1]);
            MMA_FP16(acc[2 * nt2 + 1], a, w[2], w[3]);
        }
    }

    // ---- Epilogue
    int r0 = row0 + m0 + (lane >> 2);
    int cb = 2 * (lane & 3);
    float rs0 = 0.f, rs1 = 0.f;
    if (HALF_OUT) {
        if (r0 < N_NODES)     rs0 = __ldg(&g_rs_src[r0]);
        if (r0 + 8 < N_NODES) rs1 = __ldg(&g_rs_src[r0 + 8]);
    }
    #pragma unroll
    for (int nt = 0; nt < 16; ++nt) {
        int n = nt * 8 + cb;
        float bx = __ldg(&bias[n]), by = __ldg(&bias[n + 1]);
        float v0x = fmaxf(acc[nt][0] + bx, 0.f);
        float v0y = fmaxf(acc[nt][1] + by, 0.f);
        float v1x = fmaxf(acc[nt][2] + bx, 0.f);
        float v1y = fmaxf(acc[nt][3] + by, 0.f);
        if (HALF_OUT) {
            if (r0 < N_NODES)
                *(__half2*)(out16 + (size_t)r0 * F + n) = __floats2half2_rn(v0x * rs0, v0y * rs0);
            if (r0 + 8 < N_NODES)
                *(__half2*)(out16 + (size_t)(r0 + 8) * F + n) = __floats2half2_rn(v1x * rs1, v1y * rs1);
        } else {
            if (r0 < N_NODES)
                *(float2*)(out32 + (size_t)r0 * F + n) = make_float2(v0x, v0y);
            if (r0 + 8 < N_NODES)
                *(float2*)(out32 + (size_t)(r0 + 8) * F + n) = make_float2(v1x, v1y);
        }
    }
}

// ---------------- host launch ----------------
extern "C" void kernel_launch(void* const* d_in, const int* in_sizes, int n_in,
                              void* d_out, int out_size) {
    const float* features = (const float*)d_in[0];
    const float* W1       = (const float*)d_in[1];
    const float* b1       = (const float*)d_in[2];
    const float* W2       = (const float*)d_in[3];
    const float* b2       = (const float*)d_in[4];
    const int*   src      = (const int*)d_in[5];
    const int*   dst      = (const int*)d_in[6];
    float*       out      = (float*)d_out;

    __half *h16 = nullptr, *a16 = nullptr;
    unsigned short *wh = nullptr;
    cudaGetSymbolAddress((void**)&h16, g_h16);
    cudaGetSymbolAddress((void**)&a16, g_a16);
    cudaGetSymbolAddress((void**)&wh,  g_Wh);

    cudaFuncSetAttribute(mma_gemm_kernel<0>,
                         cudaFuncAttributeMaxDynamicSharedMemorySize, GEMM_SMEM_BYTES);
    cudaFuncSetAttribute(mma_gemm_kernel<1>,
                         cudaFuncAttributeMaxDynamicSharedMemorySize, GEMM_SMEM_BYTES);

    int nblk_aggw = (N_NODES * 32 + 255) / 256;   // one warp per node
    int nblk_gemm = (N_NODES + 127) / 128;        // 782

    // K1-K5: preprocessing (deterministic each call)
    init_kernel<<<NB_NODES + 128, 256>>>(W1, W2);
    count_degs_kernel<<<NB_EDGES, 256>>>(src, dst);
    scan_block_sums_kernel<<<NPART, SCAN_B>>>();
    scan_final_kernel<<<NPART, SCAN_B>>>();
    fill_conv_kernel<<<NB_EDGES + NB_CONV, 256>>>(src, dst, features);

    // K6-K7: layer 1   (h16 -> a16 -> h16)
    aggregate16_kernel<<<nblk_aggw, 256>>>(h16, a16);
    mma_gemm_kernel<1><<<nblk_gemm, 256, GEMM_SMEM_BYTES>>>(a16, wh, b1, nullptr, h16);

    // K8-K9: layer 2   (h16 -> a16 -> out fp32)
    aggregate16_kernel<<<nblk_aggw, 256>>>(h16, a16);
    mma_gemm_kernel<0><<<nblk_gemm, 256, GEMM_SMEM_BYTES>>>(a16, wh + 128 * 128, b2, out, nullptr);
}